// round 1
// baseline (speedup 1.0000x reference)
#include <cuda_runtime.h>
#include <math.h>

// ---------------------------------------------------------------------------
// Res_GCN: 2-layer GCN + heads.
//   h   = relu(Agg(x@W1) + b1)
//   agg = Agg(h)                       (shared by both layer-2 branches)
//   feat_label   = agg@W2  + b2
//   out_pca      = agg@((W2+W2u)@Wpca^T) + folded bias
//   out_bce      = agg@(W2u@Wbce^T)      + folded bias
//   out1         = ((feat_label/||feat_label||)@Wh1^T + bh1) / 0.1
// Output layout: [out1 (N*4)] [out_pca (N*128)] [out_bce (N*128)] [feat_label (N*128)]
// ---------------------------------------------------------------------------

#define MAXN 50000
#define MAXE 800000
#define H 128

__device__ float g_h0[MAXN * H];      // x @ W1
__device__ float g_h[MAXN * H];       // relu(Agg(h0)+b1)
__device__ float g_agg[MAXN * H];     // Agg(h)
__device__ float g_dinv[MAXN];
__device__ int   g_deg[MAXN];
__device__ int   g_rowptr[MAXN + 1];
__device__ int   g_cursor[MAXN];
__device__ int   g_col[MAXE];
__device__ float g_Wbig[H * 384];     // [k][seg*128+j]: seg0=W2, seg1=pca-folded, seg2=bce-folded
__device__ float g_bbig[384];

// ------------------------- graph prep --------------------------------------

__global__ void zero_deg_kernel(int n) {
    int i = blockIdx.x * blockDim.x + threadIdx.x;
    if (i < n) g_deg[i] = 0;
}

__global__ void hist_kernel(const int* __restrict__ dst, int e) {
    int i = blockIdx.x * blockDim.x + threadIdx.x;
    if (i < e) atomicAdd(&g_deg[dst[i]], 1);
}

__global__ void dinv_kernel(int n) {
    int i = blockIdx.x * blockDim.x + threadIdx.x;
    if (i < n) g_dinv[i] = rsqrtf((float)(g_deg[i] + 1));
}

// single-block exclusive scan of g_deg -> g_rowptr, g_cursor
__global__ void scan_kernel(int n) {
    __shared__ int sdata[1024];
    __shared__ int carry_s;
    int carry = 0;
    for (int base = 0; base < n; base += 1024) {
        int i = base + threadIdx.x;
        int v = (i < n) ? g_deg[i] : 0;
        sdata[threadIdx.x] = v;
        __syncthreads();
        for (int off = 1; off < 1024; off <<= 1) {
            int t = (threadIdx.x >= off) ? sdata[threadIdx.x - off] : 0;
            __syncthreads();
            sdata[threadIdx.x] += t;
            __syncthreads();
        }
        int excl = sdata[threadIdx.x] - v;
        if (i < n) {
            g_rowptr[i] = carry + excl;
            g_cursor[i] = carry + excl;
        }
        if (threadIdx.x == 1023) carry_s = carry + sdata[1023];
        __syncthreads();
        carry = carry_s;
        __syncthreads();
    }
    if (threadIdx.x == 0) g_rowptr[n] = carry;
}

__global__ void scatter_kernel(const int* __restrict__ src, const int* __restrict__ dst, int e) {
    int i = blockIdx.x * blockDim.x + threadIdx.x;
    if (i < e) {
        int d = dst[i];
        int pos = atomicAdd(&g_cursor[d], 1);
        g_col[pos] = src[i];
    }
}

// ------------------------- aggregation (gather, warp per node) -------------

__global__ void gather_kernel(const float* __restrict__ hin, float* __restrict__ hout,
                              const float* __restrict__ bias, int n, int relu) {
    int w = (blockIdx.x * blockDim.x + threadIdx.x) >> 5;
    int lane = threadIdx.x & 31;
    if (w >= n) return;
    int beg = g_rowptr[w];
    int end = g_rowptr[w + 1];
    float dv = g_dinv[w];
    float4 hv = *(const float4*)&hin[(size_t)w * H + lane * 4];
    float4 acc = make_float4(dv * hv.x, dv * hv.y, dv * hv.z, dv * hv.w);  // self loop
    for (int e0 = beg; e0 < end; e0 += 32) {
        int idx = e0 + lane;
        int c = 0;
        float dval = 0.f;
        if (idx < end) { c = g_col[idx]; dval = g_dinv[c]; }
        int m = min(32, end - e0);
        for (int j = 0; j < m; j++) {
            int u = __shfl_sync(0xffffffffu, c, j);
            float du = __shfl_sync(0xffffffffu, dval, j);
            float4 huv = *(const float4*)&hin[(size_t)u * H + lane * 4];
            acc.x += du * huv.x;
            acc.y += du * huv.y;
            acc.z += du * huv.z;
            acc.w += du * huv.w;
        }
    }
    acc.x *= dv; acc.y *= dv; acc.z *= dv; acc.w *= dv;
    if (bias) {
        float4 b4 = *(const float4*)&bias[lane * 4];
        acc.x += b4.x; acc.y += b4.y; acc.z += b4.z; acc.w += b4.w;
    }
    if (relu) {
        acc.x = fmaxf(acc.x, 0.f); acc.y = fmaxf(acc.y, 0.f);
        acc.z = fmaxf(acc.z, 0.f); acc.w = fmaxf(acc.w, 0.f);
    }
    *(float4*)&hout[(size_t)w * H + lane * 4] = acc;
}

// ------------------------- weight folding ----------------------------------

__global__ void wprep_kernel(const float* __restrict__ W2, const float* __restrict__ W2u,
                             const float* __restrict__ Wpca, const float* __restrict__ Wbce,
                             const float* __restrict__ b2, const float* __restrict__ b2u,
                             const float* __restrict__ bpca, const float* __restrict__ bbce) {
    int k = blockIdx.x;       // 0..127 (input dim)
    int j = threadIdx.x;      // 0..127 (output dim within segment)
    int seg = blockIdx.y;     // 0..2
    float v;
    if (seg == 0) {
        v = W2[k * H + j];
    } else if (seg == 1) {
        float s = 0.f;
        for (int m = 0; m < H; m++) s += (W2[k * H + m] + W2u[k * H + m]) * Wpca[j * H + m];
        v = s;
    } else {
        float s = 0.f;
        for (int m = 0; m < H; m++) s += W2u[k * H + m] * Wbce[j * H + m];
        v = s;
    }
    g_Wbig[k * 384 + seg * H + j] = v;
    if (k == 0) {
        float b;
        if (seg == 0) {
            b = b2[j];
        } else if (seg == 1) {
            float s = 0.f;
            for (int m = 0; m < H; m++) s += (b2[m] + b2u[m]) * Wpca[j * H + m];
            b = s + bpca[j];
        } else {
            float s = 0.f;
            for (int m = 0; m < H; m++) s += b2u[m] * Wbce[j * H + m];
            b = s + bbce[j];
        }
        g_bbig[seg * H + j] = b;
    }
}

// ------------------------- GEMM (N x 128) @ (128 x OUT) --------------------
// Block: 64 rows x 128 cols (one col-tile of width 128 per blockIdx.y).
// 256 threads, each computes 8 rows x 4 cols. fp32 FMA.

__global__ void gemm_kernel(const float* __restrict__ A, const float* __restrict__ W, int ldw,
                            const float* __restrict__ bias, int n,
                            float* __restrict__ d0, float* __restrict__ d1, float* __restrict__ d2) {
    extern __shared__ float smem[];
    float* As = smem;             // 64 x 128
    float* Ws = smem + 64 * H;    // 128 x 128
    int row0 = blockIdx.x * 64;
    int colOff = blockIdx.y * H;
    int tid = threadIdx.x;

    // load W tile (128x128) as float4
    for (int i = tid; i < H * 32; i += 256) {
        int k = i >> 5;
        int j4 = (i & 31) * 4;
        *(float4*)&Ws[k * H + j4] = *(const float4*)&W[(size_t)k * ldw + colOff + j4];
    }
    // load A tile (64x128) as float4, zero-pad tail rows
    for (int i = tid; i < 64 * 32; i += 256) {
        int r = i >> 5;
        int c4 = (i & 31) * 4;
        int gr = row0 + r;
        float4 v = make_float4(0.f, 0.f, 0.f, 0.f);
        if (gr < n) v = *(const float4*)&A[(size_t)gr * H + c4];
        *(float4*)&As[r * H + c4] = v;
    }
    __syncthreads();

    int tx = tid & 31;   // col group: cols tx*4 .. tx*4+3
    int ty = tid >> 5;   // row group: rows ty*8 .. ty*8+7
    float acc[8][4];
#pragma unroll
    for (int r = 0; r < 8; r++)
#pragma unroll
        for (int c = 0; c < 4; c++) acc[r][c] = 0.f;

#pragma unroll 16
    for (int k = 0; k < H; k++) {
        float4 w4 = *(float4*)&Ws[k * H + tx * 4];
#pragma unroll
        for (int r = 0; r < 8; r++) {
            float a = As[(ty * 8 + r) * H + k];
            acc[r][0] += a * w4.x;
            acc[r][1] += a * w4.y;
            acc[r][2] += a * w4.z;
            acc[r][3] += a * w4.w;
        }
    }

    int j = colOff + tx * 4;
    int seg = j >> 7;
    int jl = j & 127;
    float* dst = (seg == 0) ? d0 : ((seg == 1) ? d1 : d2);
    float4 b4 = make_float4(0.f, 0.f, 0.f, 0.f);
    if (bias) b4 = *(const float4*)&bias[j];
#pragma unroll
    for (int r = 0; r < 8; r++) {
        int gr = row0 + ty * 8 + r;
        if (gr < n) {
            float4 o = make_float4(acc[r][0] + b4.x, acc[r][1] + b4.y,
                                   acc[r][2] + b4.z, acc[r][3] + b4.w);
            *(float4*)&dst[(size_t)gr * H + jl] = o;
        }
    }
}

// ------------------------- out1 head ---------------------------------------

__global__ void out1_kernel(const float* __restrict__ fl, const float* __restrict__ Wh1,
                            const float* __restrict__ bh1, float* __restrict__ out1, int n) {
    int w = (blockIdx.x * blockDim.x + threadIdx.x) >> 5;
    int lane = threadIdx.x & 31;
    if (w >= n) return;
    float4 f = *(const float4*)&fl[(size_t)w * H + lane * 4];
    float ss = f.x * f.x + f.y * f.y + f.z * f.z + f.w * f.w;
#pragma unroll
    for (int off = 16; off > 0; off >>= 1) ss += __shfl_xor_sync(0xffffffffu, ss, off);
    float nrm = fmaxf(sqrtf(ss), 1e-12f);
    float inv = 10.f / nrm;
#pragma unroll
    for (int j = 0; j < 4; j++) {
        float4 wv = *(const float4*)&Wh1[j * H + lane * 4];
        float p = f.x * wv.x + f.y * wv.y + f.z * wv.z + f.w * wv.w;
#pragma unroll
        for (int off = 16; off > 0; off >>= 1) p += __shfl_xor_sync(0xffffffffu, p, off);
        if (lane == 0) out1[(size_t)w * 4 + j] = p * inv + bh1[j] * 10.f;
    }
}

// ------------------------- launch ------------------------------------------

extern "C" void kernel_launch(void* const* d_in, const int* in_sizes, int n_in,
                              void* d_out, int out_size) {
    const float* x    = (const float*)d_in[0];
    const int*   ei   = (const int*)d_in[1];
    const float* W1   = (const float*)d_in[2];
    const float* b1   = (const float*)d_in[3];
    const float* W2   = (const float*)d_in[4];
    const float* b2   = (const float*)d_in[5];
    const float* W2u  = (const float*)d_in[6];
    const float* b2u  = (const float*)d_in[7];
    const float* Wh1  = (const float*)d_in[8];
    const float* bh1  = (const float*)d_in[9];
    const float* Wpca = (const float*)d_in[10];
    const float* bpca = (const float*)d_in[11];
    const float* Wbce = (const float*)d_in[12];
    const float* bbce = (const float*)d_in[13];

    int n = in_sizes[0] / H;
    int e = in_sizes[1] / 2;
    const int* src = ei;
    const int* dst = ei + e;

    float* out  = (float*)d_out;
    float* out1 = out;
    float* opca = out + (size_t)n * 4;
    float* obce = opca + (size_t)n * H;
    float* flab = obce + (size_t)n * H;

    void *p_h0, *p_h, *p_agg, *p_Wbig, *p_bbig;
    cudaGetSymbolAddress(&p_h0, g_h0);
    cudaGetSymbolAddress(&p_h, g_h);
    cudaGetSymbolAddress(&p_agg, g_agg);
    cudaGetSymbolAddress(&p_Wbig, g_Wbig);
    cudaGetSymbolAddress(&p_bbig, g_bbig);

    const int smem_gemm = (64 * H + H * H) * sizeof(float);  // 96 KB
    cudaFuncSetAttribute(gemm_kernel, cudaFuncAttributeMaxDynamicSharedMemorySize, smem_gemm);

    int nb_n = (n + 255) / 256;
    int nb_e = (e + 255) / 256;
    int nb_w = (n + 7) / 8;          // warp-per-node kernels, 256 threads = 8 warps
    int nb_g = (n + 63) / 64;        // gemm row tiles

    // graph prep
    zero_deg_kernel<<<nb_n, 256>>>(n);
    hist_kernel<<<nb_e, 256>>>(dst, e);
    dinv_kernel<<<nb_n, 256>>>(n);
    scan_kernel<<<1, 1024>>>(n);
    scatter_kernel<<<nb_e, 256>>>(src, dst, e);

    // layer 1: h0 = x @ W1 ; h = relu(Agg(h0) + b1)
    gemm_kernel<<<dim3(nb_g, 1), 256, smem_gemm>>>(x, W1, H, nullptr, n,
                                                   (float*)p_h0, (float*)p_h0, (float*)p_h0);
    gather_kernel<<<nb_w, 256>>>((const float*)p_h0, (float*)p_h, b1, n, 1);

    // fold layer-2 + head weights
    wprep_kernel<<<dim3(H, 3), H>>>(W2, W2u, Wpca, Wbce, b2, b2u, bpca, bbce);

    // layer 2: agg = Agg(h) ; fused GEMM -> feat_label / out_pca / out_bce
    gather_kernel<<<nb_w, 256>>>((const float*)p_h, (float*)p_agg, nullptr, n, 0);
    gemm_kernel<<<dim3(nb_g, 3), 256, smem_gemm>>>((const float*)p_agg, (const float*)p_Wbig, 384,
                                                   (const float*)p_bbig, n,
                                                   flab, opca, obce);

    // out1 head from feat_label
    out1_kernel<<<nb_w, 256>>>(flab, Wh1, bh1, out1, n);
}

// round 3
// speedup vs baseline: 1.4237x; 1.4237x over previous
#include <cuda_runtime.h>
#include <cuda_bf16.h>
#include <cstdint>
#include <math.h>

// ---------------------------------------------------------------------------
// Res_GCN: 2-layer GCN + heads, bf16-split tensor-core GEMMs.
//   h   = relu(Agg(x@W1) + b1)
//   agg = Agg(h)                      (shared by both layer-2 branches)
//   feat_label = agg@W2 + b2
//   out_pca    = agg@((W2+W2u)Wpca^T) + folded bias
//   out_bce    = agg@(W2u Wbce^T)     + folded bias
//   out1       = ((feat_label/||.||)@Wh1^T + bh1)/0.1
// ---------------------------------------------------------------------------

#define MAXN 50000
#define MAXE 800000
#define H 128

__device__ float g_h0[MAXN * H];              // x @ W1
__device__ float g_h[MAXN * H];               // relu(Agg(h0)+b1)
__device__ __nv_bfloat16 g_aggh[MAXN * H];    // Agg(h) hi
__device__ __nv_bfloat16 g_aggl[MAXN * H];    // Agg(h) lo
__device__ __nv_bfloat16 g_xh[MAXN * H];      // x hi
__device__ __nv_bfloat16 g_xl[MAXN * H];      // x lo
__device__ __nv_bfloat16 g_W1h[H * H];
__device__ __nv_bfloat16 g_W1l[H * H];
__device__ __nv_bfloat16 g_Wbh[H * 384];      // folded layer-2 weights hi
__device__ __nv_bfloat16 g_Wbl[H * 384];      // folded layer-2 weights lo
__device__ float g_bbig[384];
__device__ float g_dinv[MAXN];
__device__ int   g_deg[MAXN];
__device__ int   g_rowptr[MAXN + 1];
__device__ int   g_cursor[MAXN];
__device__ int   g_col[MAXE];
__device__ int   g_bsum[64];
__device__ int   g_boff[64];

// ------------------------- helpers -----------------------------------------

__device__ __forceinline__ void split_bf16(float a, unsigned short& hi, unsigned short& lo) {
    __nv_bfloat16 h = __float2bfloat16_rn(a);
    float r = a - __bfloat162float(h);
    __nv_bfloat16 l = __float2bfloat16_rn(r);
    hi = *(unsigned short*)&h;
    lo = *(unsigned short*)&l;
}

__device__ __forceinline__ void ldsm4(uint32_t& r0, uint32_t& r1, uint32_t& r2, uint32_t& r3,
                                      uint32_t addr) {
    asm volatile("ldmatrix.sync.aligned.m8n8.x4.shared.b16 {%0,%1,%2,%3}, [%4];\n"
                 : "=r"(r0), "=r"(r1), "=r"(r2), "=r"(r3) : "r"(addr));
}

__device__ __forceinline__ void ldsm4t(uint32_t& r0, uint32_t& r1, uint32_t& r2, uint32_t& r3,
                                       uint32_t addr) {
    asm volatile("ldmatrix.sync.aligned.m8n8.x4.trans.shared.b16 {%0,%1,%2,%3}, [%4];\n"
                 : "=r"(r0), "=r"(r1), "=r"(r2), "=r"(r3) : "r"(addr));
}

__device__ __forceinline__ void mma_bf16(float* d, const uint32_t* a, const uint32_t* b) {
    asm volatile("mma.sync.aligned.m16n8k16.row.col.f32.bf16.bf16.f32 "
                 "{%0,%1,%2,%3}, {%4,%5,%6,%7}, {%8,%9}, {%0,%1,%2,%3};\n"
                 : "+f"(d[0]), "+f"(d[1]), "+f"(d[2]), "+f"(d[3])
                 : "r"(a[0]), "r"(a[1]), "r"(a[2]), "r"(a[3]), "r"(b[0]), "r"(b[1]));
}

// ------------------------- graph prep --------------------------------------

__global__ void zero_deg_kernel(int n) {
    int i = blockIdx.x * blockDim.x + threadIdx.x;
    if (i < n) g_deg[i] = 0;
}

__global__ void hist_kernel(const int* __restrict__ dst, int e) {
    int i = blockIdx.x * blockDim.x + threadIdx.x;
    if (i < e) atomicAdd(&g_deg[dst[i]], 1);
}

__global__ void dinv_kernel(int n) {
    int i = blockIdx.x * blockDim.x + threadIdx.x;
    if (i < n) g_dinv[i] = rsqrtf((float)(g_deg[i] + 1));
}

// block-local scan: 256 threads x 4 items = 1024 per block
__global__ void blockscan_kernel(int n) {
    __shared__ int s[256];
    int t = threadIdx.x;
    int base = blockIdx.x * 1024 + t * 4;
    int v0 = (base + 0 < n) ? g_deg[base + 0] : 0;
    int v1 = (base + 1 < n) ? g_deg[base + 1] : 0;
    int v2 = (base + 2 < n) ? g_deg[base + 2] : 0;
    int v3 = (base + 3 < n) ? g_deg[base + 3] : 0;
    int sum = v0 + v1 + v2 + v3;
    s[t] = sum;
    __syncthreads();
    for (int off = 1; off < 256; off <<= 1) {
        int tv = (t >= off) ? s[t - off] : 0;
        __syncthreads();
        s[t] += tv;
        __syncthreads();
    }
    int run = s[t] - sum;
    if (base + 0 < n) { g_rowptr[base + 0] = run; } run += v0;
    if (base + 1 < n) { g_rowptr[base + 1] = run; } run += v1;
    if (base + 2 < n) { g_rowptr[base + 2] = run; } run += v2;
    if (base + 3 < n) { g_rowptr[base + 3] = run; }
    if (t == 255) g_bsum[blockIdx.x] = s[255];
}

__global__ void bsum_scan_kernel(int nb) {
    __shared__ int s[64];
    int t = threadIdx.x;
    int v = (t < nb) ? g_bsum[t] : 0;
    s[t] = v;
    __syncthreads();
    for (int off = 1; off < 64; off <<= 1) {
        int tv = (t >= off) ? s[t - off] : 0;
        __syncthreads();
        s[t] += tv;
        __syncthreads();
    }
    g_boff[t] = s[t] - v;
}

__global__ void addoff_kernel(int n, int e) {
    int i = blockIdx.x * blockDim.x + threadIdx.x;
    if (i < n) {
        int r = g_rowptr[i] + g_boff[i >> 10];
        g_rowptr[i] = r;
        g_cursor[i] = r;
    }
    if (i == 0) g_rowptr[n] = e;
}

__global__ void scatter_kernel(const int* __restrict__ src, const int* __restrict__ dst, int e) {
    int i = blockIdx.x * blockDim.x + threadIdx.x;
    if (i < e) {
        int d = dst[i];
        int pos = atomicAdd(&g_cursor[d], 1);
        g_col[pos] = src[i];
    }
}

// ------------------------- split fp32 -> bf16 hi/lo ------------------------

__global__ void split_kernel(const float* __restrict__ a, __nv_bfloat16* __restrict__ hi,
                             __nv_bfloat16* __restrict__ lo, int n4) {
    int i = blockIdx.x * blockDim.x + threadIdx.x;
    if (i >= n4) return;
    float4 v = ((const float4*)a)[i];
    ushort4 h, l;
    split_bf16(v.x, h.x, l.x);
    split_bf16(v.y, h.y, l.y);
    split_bf16(v.z, h.z, l.z);
    split_bf16(v.w, h.w, l.w);
    ((ushort4*)hi)[i] = h;
    ((ushort4*)lo)[i] = l;
}

// ------------------------- aggregation (gather, warp per node) -------------

__global__ void gather_kernel(const float* __restrict__ hin, float* __restrict__ outf,
                              __nv_bfloat16* __restrict__ outh, __nv_bfloat16* __restrict__ outl,
                              const float* __restrict__ bias, int n, int relu) {
    int w = (blockIdx.x * blockDim.x + threadIdx.x) >> 5;
    int lane = threadIdx.x & 31;
    if (w >= n) return;
    int beg = g_rowptr[w];
    int end = g_rowptr[w + 1];
    float dv = g_dinv[w];
    float4 hv = *(const float4*)&hin[(size_t)w * H + lane * 4];
    float4 a0 = make_float4(dv * hv.x, dv * hv.y, dv * hv.z, dv * hv.w);  // self loop
    float4 a1 = make_float4(0.f, 0.f, 0.f, 0.f);
    float4 a2 = make_float4(0.f, 0.f, 0.f, 0.f);
    float4 a3 = make_float4(0.f, 0.f, 0.f, 0.f);
    for (int e0 = beg; e0 < end; e0 += 32) {
        int idx = e0 + lane;
        int c = 0;
        float dval = 0.f;
        if (idx < end) { c = g_col[idx]; dval = g_dinv[c]; }
        int m = min(32, end - e0);
        int j = 0;
        for (; j + 4 <= m; j += 4) {
            int u0 = __shfl_sync(0xffffffffu, c, j);
            int u1 = __shfl_sync(0xffffffffu, c, j + 1);
            int u2 = __shfl_sync(0xffffffffu, c, j + 2);
            int u3 = __shfl_sync(0xffffffffu, c, j + 3);
            float d0 = __shfl_sync(0xffffffffu, dval, j);
            float d1 = __shfl_sync(0xffffffffu, dval, j + 1);
            float d2 = __shfl_sync(0xffffffffu, dval, j + 2);
            float d3 = __shfl_sync(0xffffffffu, dval, j + 3);
            float4 h0v = *(const float4*)&hin[(size_t)u0 * H + lane * 4];
            float4 h1v = *(const float4*)&hin[(size_t)u1 * H + lane * 4];
            float4 h2v = *(const float4*)&hin[(size_t)u2 * H + lane * 4];
            float4 h3v = *(const float4*)&hin[(size_t)u3 * H + lane * 4];
            a0.x += d0 * h0v.x; a0.y += d0 * h0v.y; a0.z += d0 * h0v.z; a0.w += d0 * h0v.w;
            a1.x += d1 * h1v.x; a1.y += d1 * h1v.y; a1.z += d1 * h1v.z; a1.w += d1 * h1v.w;
            a2.x += d2 * h2v.x; a2.y += d2 * h2v.y; a2.z += d2 * h2v.z; a2.w += d2 * h2v.w;
            a3.x += d3 * h3v.x; a3.y += d3 * h3v.y; a3.z += d3 * h3v.z; a3.w += d3 * h3v.w;
        }
        for (; j < m; j++) {
            int u = __shfl_sync(0xffffffffu, c, j);
            float du = __shfl_sync(0xffffffffu, dval, j);
            float4 huv = *(const float4*)&hin[(size_t)u * H + lane * 4];
            a0.x += du * huv.x; a0.y += du * huv.y; a0.z += du * huv.z; a0.w += du * huv.w;
        }
    }
    float4 acc = make_float4((a0.x + a1.x) + (a2.x + a3.x),
                             (a0.y + a1.y) + (a2.y + a3.y),
                             (a0.z + a1.z) + (a2.z + a3.z),
                             (a0.w + a1.w) + (a2.w + a3.w));
    acc.x *= dv; acc.y *= dv; acc.z *= dv; acc.w *= dv;
    if (bias) {
        float4 b4 = *(const float4*)&bias[lane * 4];
        acc.x += b4.x; acc.y += b4.y; acc.z += b4.z; acc.w += b4.w;
    }
    if (relu) {
        acc.x = fmaxf(acc.x, 0.f); acc.y = fmaxf(acc.y, 0.f);
        acc.z = fmaxf(acc.z, 0.f); acc.w = fmaxf(acc.w, 0.f);
    }
    if (outf) {
        *(float4*)&outf[(size_t)w * H + lane * 4] = acc;
    } else {
        ushort4 h, l;
        split_bf16(acc.x, h.x, l.x);
        split_bf16(acc.y, h.y, l.y);
        split_bf16(acc.z, h.z, l.z);
        split_bf16(acc.w, h.w, l.w);
        *(ushort4*)&outh[(size_t)w * H + lane * 4] = h;
        *(ushort4*)&outl[(size_t)w * H + lane * 4] = l;
    }
}

// ------------------------- weight folding ----------------------------------

__global__ void wprep_kernel(const float* __restrict__ W2, const float* __restrict__ W2u,
                             const float* __restrict__ Wpca, const float* __restrict__ Wbce,
                             const float* __restrict__ b2, const float* __restrict__ b2u,
                             const float* __restrict__ bpca, const float* __restrict__ bbce) {
    int k = blockIdx.x;       // 0..127 (input dim)
    int j = threadIdx.x;      // 0..127 (output dim within segment)
    int seg = blockIdx.y;     // 0..2
    float v;
    if (seg == 0) {
        v = W2[k * H + j];
    } else if (seg == 1) {
        float s = 0.f;
        for (int m = 0; m < H; m++) s += (W2[k * H + m] + W2u[k * H + m]) * Wpca[j * H + m];
        v = s;
    } else {
        float s = 0.f;
        for (int m = 0; m < H; m++) s += W2u[k * H + m] * Wbce[j * H + m];
        v = s;
    }
    unsigned short hi, lo;
    split_bf16(v, hi, lo);
    g_Wbh[k * 384 + seg * H + j] = *(__nv_bfloat16*)&hi;
    g_Wbl[k * 384 + seg * H + j] = *(__nv_bfloat16*)&lo;
    if (k == 0) {
        float b;
        if (seg == 0) {
            b = b2[j];
        } else if (seg == 1) {
            float s = 0.f;
            for (int m = 0; m < H; m++) s += (b2[m] + b2u[m]) * Wpca[j * H + m];
            b = s + bpca[j];
        } else {
            float s = 0.f;
            for (int m = 0; m < H; m++) s += b2u[m] * Wbce[j * H + m];
            b = s + bbce[j];
        }
        g_bbig[seg * H + j] = b;
    }
}

// ------------------------- bf16-split tensor GEMM --------------------------
// D[n x 128seg] = A[n x 128] @ W[128 x ldw](col tile) + bias
// Block: 128 rows x 128 cols, K=128 in smem. 8 warps, warp tile 32x64.
// acc += Ah*Wh + Ah*Wl + Al*Wh  (fp32 accumulate) ~ fp32 accuracy.

#define APAD 136  // bf16 elements per padded row (272 B; conflict-free ldmatrix)

__global__ __launch_bounds__(256, 1)
void gemm_mma_kernel(const __nv_bfloat16* __restrict__ Ah, const __nv_bfloat16* __restrict__ Al,
                     const __nv_bfloat16* __restrict__ Wh, const __nv_bfloat16* __restrict__ Wl,
                     int ldw, const float* __restrict__ bias, int n,
                     float* __restrict__ d0, float* __restrict__ d1, float* __restrict__ d2) {
    extern __shared__ unsigned short smem[];
    unsigned short* Ah_s = smem;                    // 128 x APAD
    unsigned short* Al_s = Ah_s + 128 * APAD;
    unsigned short* Wh_s = Al_s + 128 * APAD;
    unsigned short* Wl_s = Wh_s + 128 * APAD;

    int tid = threadIdx.x;
    int row0 = blockIdx.x * 128;
    int colOff = blockIdx.y * 128;

    // load A tiles (guard rows), 16B chunks
    const uint4 zero4 = make_uint4(0, 0, 0, 0);
    for (int i = tid; i < 128 * 16; i += 256) {
        int r = i >> 4;
        int c = i & 15;           // 16B chunk = 8 bf16
        int gr = row0 + r;
        uint4 vh = zero4, vl = zero4;
        if (gr < n) {
            vh = ((const uint4*)(Ah + (size_t)gr * H))[c];
            vl = ((const uint4*)(Al + (size_t)gr * H))[c];
        }
        *(uint4*)&Ah_s[r * APAD + c * 8] = vh;
        *(uint4*)&Al_s[r * APAD + c * 8] = vl;
    }
    // load W tiles
    for (int i = tid; i < 128 * 16; i += 256) {
        int k = i >> 4;
        int c = i & 15;
        *(uint4*)&Wh_s[k * APAD + c * 8] = ((const uint4*)(Wh + (size_t)k * ldw + colOff))[c];
        *(uint4*)&Wl_s[k * APAD + c * 8] = ((const uint4*)(Wl + (size_t)k * ldw + colOff))[c];
    }
    __syncthreads();

    int lane = tid & 31;
    int warp = tid >> 5;
    int m0 = (warp >> 1) * 32;    // warp rows m0..m0+31
    int n0 = (warp & 1) * 64;     // warp cols n0..n0+63
    int lrow = lane & 15;
    int lsel = lane >> 4;

    uint32_t baseAh = (uint32_t)__cvta_generic_to_shared(&Ah_s[(m0 + lrow) * APAD + lsel * 8]);
    uint32_t baseAl = (uint32_t)__cvta_generic_to_shared(&Al_s[(m0 + lrow) * APAD + lsel * 8]);
    uint32_t baseWh = (uint32_t)__cvta_generic_to_shared(&Wh_s[lrow * APAD + n0 + lsel * 8]);
    uint32_t baseWl = (uint32_t)__cvta_generic_to_shared(&Wl_s[lrow * APAD + n0 + lsel * 8]);

    float acc[2][8][4];
#pragma unroll
    for (int mt = 0; mt < 2; mt++)
#pragma unroll
        for (int nt = 0; nt < 8; nt++)
#pragma unroll
            for (int q = 0; q < 4; q++) acc[mt][nt][q] = 0.f;

    for (int k0 = 0; k0 < 128; k0 += 16) {
        uint32_t ah[2][4], al[2][4], wh[8][2], wl[8][2];
#pragma unroll
        for (int mt = 0; mt < 2; mt++) {
            uint32_t off = (uint32_t)(mt * 16 * APAD + k0) * 2;
            ldsm4(ah[mt][0], ah[mt][1], ah[mt][2], ah[mt][3], baseAh + off);
            ldsm4(al[mt][0], al[mt][1], al[mt][2], al[mt][3], baseAl + off);
        }
#pragma unroll
        for (int nt2 = 0; nt2 < 4; nt2++) {
            uint32_t off = (uint32_t)(k0 * APAD + nt2 * 16) * 2;
            ldsm4t(wh[2 * nt2][0], wh[2 * nt2][1], wh[2 * nt2 + 1][0], wh[2 * nt2 + 1][1],
                   baseWh + off);
            ldsm4t(wl[2 * nt2][0], wl[2 * nt2][1], wl[2 * nt2 + 1][0], wl[2 * nt2 + 1][1],
                   baseWl + off);
        }
#pragma unroll
        for (int mt = 0; mt < 2; mt++)
#pragma unroll
            for (int nt = 0; nt < 8; nt++) {
                mma_bf16(acc[mt][nt], ah[mt], wh[nt]);
                mma_bf16(acc[mt][nt], ah[mt], wl[nt]);
                mma_bf16(acc[mt][nt], al[mt], wh[nt]);
            }
    }

    // epilogue
    float* dst = (blockIdx.y == 0) ? d0 : ((blockIdx.y == 1) ? d1 : d2);
    int g = lane >> 2;
    int tg = lane & 3;
#pragma unroll
    for (int mt = 0; mt < 2; mt++) {
#pragma unroll
        for (int nt = 0; nt < 8; nt++) {
            int colL = n0 + nt * 8 + 2 * tg;
            float bx = 0.f, by = 0.f;
            if (bias) { bx = bias[colOff + colL]; by = bias[colOff + colL + 1]; }
            int gr0 = row0 + m0 + mt * 16 + g;
            if (gr0 < n) {
                float2 o = make_float2(acc[mt][nt][0] + bx, acc[mt][nt][1] + by);
                *(float2*)&dst[(size_t)gr0 * H + colL] = o;
            }
            int gr1 = gr0 + 8;
            if (gr1 < n) {
                float2 o = make_float2(acc[mt][nt][2] + bx, acc[mt][nt][3] + by);
                *(float2*)&dst[(size_t)gr1 * H + colL] = o;
            }
        }
    }
}

// ------------------------- out1 head ---------------------------------------

__global__ void out1_kernel(const float* __restrict__ fl, const float* __restrict__ Wh1,
                            const float* __restrict__ bh1, float* __restrict__ out1, int n) {
    int w = (blockIdx.x * blockDim.x + threadIdx.x) >> 5;
    int lane = threadIdx.x & 31;
    if (w >= n) return;
    float4 f = *(const float4*)&fl[(size_t)w * H + lane * 4];
    float ss = f.x * f.x + f.y * f.y + f.z * f.z + f.w * f.w;
#pragma unroll
    for (int off = 16; off > 0; off >>= 1) ss += __shfl_xor_sync(0xffffffffu, ss, off);
    float nrm = fmaxf(sqrtf(ss), 1e-12f);
    float inv = 10.f / nrm;
#pragma unroll
    for (int j = 0; j < 4; j++) {
        float4 wv = *(const float4*)&Wh1[j * H + lane * 4];
        float p = f.x * wv.x + f.y * wv.y + f.z * wv.z + f.w * wv.w;
#pragma unroll
        for (int off = 16; off > 0; off >>= 1) p += __shfl_xor_sync(0xffffffffu, p, off);
        if (lane == 0) out1[(size_t)w * 4 + j] = p * inv + bh1[j] * 10.f;
    }
}

// ------------------------- launch ------------------------------------------

extern "C" void kernel_launch(void* const* d_in, const int* in_sizes, int n_in,
                              void* d_out, int out_size) {
    const float* x    = (const float*)d_in[0];
    const int*   ei   = (const int*)d_in[1];
    const float* W1   = (const float*)d_in[2];
    const float* b1   = (const float*)d_in[3];
    const float* W2   = (const float*)d_in[4];
    const float* b2   = (const float*)d_in[5];
    const float* W2u  = (const float*)d_in[6];
    const float* b2u  = (const float*)d_in[7];
    const float* Wh1  = (const float*)d_in[8];
    const float* bh1  = (const float*)d_in[9];
    const float* Wpca = (const float*)d_in[10];
    const float* bpca = (const float*)d_in[11];
    const float* Wbce = (const float*)d_in[12];
    const float* bbce = (const float*)d_in[13];

    int n = in_sizes[0] / H;
    int e = in_sizes[1] / 2;
    const int* src = ei;
    const int* dst = ei + e;

    float* out  = (float*)d_out;
    float* out1 = out;
    float* opca = out + (size_t)n * 4;
    float* obce = opca + (size_t)n * H;
    float* flab = obce + (size_t)n * H;

    void *p_h0, *p_h, *p_aggh, *p_aggl, *p_xh, *p_xl, *p_W1h, *p_W1l, *p_Wbh, *p_Wbl, *p_bbig;
    cudaGetSymbolAddress(&p_h0, g_h0);
    cudaGetSymbolAddress(&p_h, g_h);
    cudaGetSymbolAddress(&p_aggh, g_aggh);
    cudaGetSymbolAddress(&p_aggl, g_aggl);
    cudaGetSymbolAddress(&p_xh, g_xh);
    cudaGetSymbolAddress(&p_xl, g_xl);
    cudaGetSymbolAddress(&p_W1h, g_W1h);
    cudaGetSymbolAddress(&p_W1l, g_W1l);
    cudaGetSymbolAddress(&p_Wbh, g_Wbh);
    cudaGetSymbolAddress(&p_Wbl, g_Wbl);
    cudaGetSymbolAddress(&p_bbig, g_bbig);

    const int smem_gemm = 4 * 128 * APAD * 2;  // 139264 B
    cudaFuncSetAttribute(gemm_mma_kernel, cudaFuncAttributeMaxDynamicSharedMemorySize, smem_gemm);

    int nb_n = (n + 255) / 256;
    int nb_e = (e + 255) / 256;
    int nb_w = (n + 7) / 8;            // warp-per-node, 256 threads = 8 warps
    int nb_g = (n + 127) / 128;        // gemm row tiles
    int nb_s = (n + 1023) / 1024;      // scan blocks

    // graph prep
    zero_deg_kernel<<<nb_n, 256>>>(n);
    split_kernel<<<(n * 32 + 255) / 256, 256>>>(x, (__nv_bfloat16*)p_xh, (__nv_bfloat16*)p_xl, n * 32);
    split_kernel<<<(128 * 32 + 255) / 256, 256>>>(W1, (__nv_bfloat16*)p_W1h, (__nv_bfloat16*)p_W1l, 128 * 32);
    hist_kernel<<<nb_e, 256>>>(dst, e);
    dinv_kernel<<<nb_n, 256>>>(n);
    blockscan_kernel<<<nb_s, 256>>>(n);
    bsum_scan_kernel<<<1, 64>>>(nb_s);
    addoff_kernel<<<nb_n, 256>>>(n, e);
    scatter_kernel<<<nb_e, 256>>>(src, dst, e);

    // layer 1: h0 = x @ W1 (tensor), h = relu(Agg(h0) + b1)
    gemm_mma_kernel<<<dim3(nb_g, 1), 256, smem_gemm>>>(
        (const __nv_bfloat16*)p_xh, (const __nv_bfloat16*)p_xl,
        (const __nv_bfloat16*)p_W1h, (const __nv_bfloat16*)p_W1l, H, nullptr, n,
        (float*)p_h0, (float*)p_h0, (float*)p_h0);
    gather_kernel<<<nb_w, 256>>>((const float*)p_h0, (float*)p_h, nullptr, nullptr, b1, n, 1);

    // fold layer-2 + head weights (bf16 split)
    wprep_kernel<<<dim3(H, 3), H>>>(W2, W2u, Wpca, Wbce, b2, b2u, bpca, bbce);

    // layer 2: agg = Agg(h) (split bf16 out) ; fused GEMM -> flab/opca/obce
    gather_kernel<<<nb_w, 256>>>((const float*)p_h, nullptr,
                                 (__nv_bfloat16*)p_aggh, (__nv_bfloat16*)p_aggl, nullptr, n, 0);
    gemm_mma_kernel<<<dim3(nb_g, 3), 256, smem_gemm>>>(
        (const __nv_bfloat16*)p_aggh, (const __nv_bfloat16*)p_aggl,
        (const __nv_bfloat16*)p_Wbh, (const __nv_bfloat16*)p_Wbl, 384,
        (const float*)p_bbig, n, flab, opca, obce);

    // out1 head from feat_label
    out1_kernel<<<nb_w, 256>>>(flab, Wh1, bh1, out1, n);
}

// round 6
// speedup vs baseline: 1.4757x; 1.0365x over previous
#include <cuda_runtime.h>
#include <cuda_bf16.h>
#include <cstdint>
#include <math.h>

// ---------------------------------------------------------------------------
// Res_GCN: 2-layer GCN + heads, bf16-split tensor-core GEMMs.
//   h   = relu(Agg(x@W1) + b1)
//   agg = Agg(h)                      (shared by both layer-2 branches)
//   feat_label = agg@W2 + b2
//   out_pca    = agg@((W2+W2u)Wpca^T) + folded bias
//   out_bce    = agg@(W2u Wbce^T)     + folded bias
//   out1       = ((feat_label/||.||)@Wh1^T + bh1)/0.1
// GEMMs consume fp32 directly (in-kernel bf16 hi/lo split) or pre-split bf16.
// ---------------------------------------------------------------------------

#define MAXN 50000
#define MAXE 800000
#define H 128

__device__ float g_h0[MAXN * H];              // x @ W1
__device__ float g_h[MAXN * H];               // relu(Agg(h0)+b1)
__device__ __nv_bfloat16 g_aggh[MAXN * H];    // Agg(h) hi
__device__ __nv_bfloat16 g_aggl[MAXN * H];    // Agg(h) lo
__device__ __nv_bfloat16 g_Wbh[H * 384];      // folded layer-2 weights hi
__device__ __nv_bfloat16 g_Wbl[H * 384];      // folded layer-2 weights lo
__device__ float g_bbig[384];
__device__ float g_dinv[MAXN];
__device__ int   g_deg[MAXN];
__device__ int   g_rowptr[MAXN + 1];
__device__ int   g_cursor[MAXN];
__device__ int   g_col[MAXE];
__device__ int   g_bsum[64];
__device__ int   g_boff[64];

// ------------------------- helpers -----------------------------------------

__device__ __forceinline__ void split_bf16(float a, unsigned short& hi, unsigned short& lo) {
    __nv_bfloat16 h = __float2bfloat16_rn(a);
    float r = a - __bfloat162float(h);
    __nv_bfloat16 l = __float2bfloat16_rn(r);
    hi = *(unsigned short*)&h;
    lo = *(unsigned short*)&l;
}

__device__ __forceinline__ void ldsm4(uint32_t& r0, uint32_t& r1, uint32_t& r2, uint32_t& r3,
                                      uint32_t addr) {
    asm volatile("ldmatrix.sync.aligned.m8n8.x4.shared.b16 {%0,%1,%2,%3}, [%4];\n"
                 : "=r"(r0), "=r"(r1), "=r"(r2), "=r"(r3) : "r"(addr));
}

__device__ __forceinline__ void ldsm4t(uint32_t& r0, uint32_t& r1, uint32_t& r2, uint32_t& r3,
                                       uint32_t addr) {
    asm volatile("ldmatrix.sync.aligned.m8n8.x4.trans.shared.b16 {%0,%1,%2,%3}, [%4];\n"
                 : "=r"(r0), "=r"(r1), "=r"(r2), "=r"(r3) : "r"(addr));
}

__device__ __forceinline__ void mma_bf16(float* d, const uint32_t* a, const uint32_t* b) {
    asm volatile("mma.sync.aligned.m16n8k16.row.col.f32.bf16.bf16.f32 "
                 "{%0,%1,%2,%3}, {%4,%5,%6,%7}, {%8,%9}, {%0,%1,%2,%3};\n"
                 : "+f"(d[0]), "+f"(d[1]), "+f"(d[2]), "+f"(d[3])
                 : "r"(a[0]), "r"(a[1]), "r"(a[2]), "r"(a[3]), "r"(b[0]), "r"(b[1]));
}

// ------------------------- graph prep --------------------------------------

__global__ void zero_deg_kernel(int n) {
    int i = blockIdx.x * blockDim.x + threadIdx.x;
    if (i < n) g_deg[i] = 0;
}

__global__ void hist_kernel(const int* __restrict__ dst, int e) {
    int i = (blockIdx.x * blockDim.x + threadIdx.x) * 4;
    if (i + 3 < e) {
        int4 d = *(const int4*)&dst[i];
        atomicAdd(&g_deg[d.x], 1);
        atomicAdd(&g_deg[d.y], 1);
        atomicAdd(&g_deg[d.z], 1);
        atomicAdd(&g_deg[d.w], 1);
    } else {
        for (int j = i; j < e; j++) atomicAdd(&g_deg[dst[j]], 1);
    }
}

// block-local scan: 256 threads x 4 items = 1024 per block; also emits dinv
__global__ void blockscan_kernel(int n) {
    __shared__ int s[256];
    int t = threadIdx.x;
    int base = blockIdx.x * 1024 + t * 4;
    int v0 = (base + 0 < n) ? g_deg[base + 0] : 0;
    int v1 = (base + 1 < n) ? g_deg[base + 1] : 0;
    int v2 = (base + 2 < n) ? g_deg[base + 2] : 0;
    int v3 = (base + 3 < n) ? g_deg[base + 3] : 0;
    if (base + 0 < n) g_dinv[base + 0] = rsqrtf((float)(v0 + 1));
    if (base + 1 < n) g_dinv[base + 1] = rsqrtf((float)(v1 + 1));
    if (base + 2 < n) g_dinv[base + 2] = rsqrtf((float)(v2 + 1));
    if (base + 3 < n) g_dinv[base + 3] = rsqrtf((float)(v3 + 1));
    int sum = v0 + v1 + v2 + v3;
    s[t] = sum;
    __syncthreads();
    for (int off = 1; off < 256; off <<= 1) {
        int tv = (t >= off) ? s[t - off] : 0;
        __syncthreads();
        s[t] += tv;
        __syncthreads();
    }
    int run = s[t] - sum;
    if (base + 0 < n) { g_rowptr[base + 0] = run; } run += v0;
    if (base + 1 < n) { g_rowptr[base + 1] = run; } run += v1;
    if (base + 2 < n) { g_rowptr[base + 2] = run; } run += v2;
    if (base + 3 < n) { g_rowptr[base + 3] = run; }
    if (t == 255) g_bsum[blockIdx.x] = s[255];
}

__global__ void bsum_scan_kernel(int nb) {
    __shared__ int s[64];
    int t = threadIdx.x;
    int v = (t < nb) ? g_bsum[t] : 0;
    s[t] = v;
    __syncthreads();
    for (int off = 1; off < 64; off <<= 1) {
        int tv = (t >= off) ? s[t - off] : 0;
        __syncthreads();
        s[t] += tv;
        __syncthreads();
    }
    g_boff[t] = s[t] - v;
}

__global__ void addoff_kernel(int n, int e) {
    int i = blockIdx.x * blockDim.x + threadIdx.x;
    if (i < n) {
        int r = g_rowptr[i] + g_boff[i >> 10];
        g_rowptr[i] = r;
        g_cursor[i] = r;
    }
    if (i == 0) g_rowptr[n] = e;
}

__global__ void scatter_kernel(const int* __restrict__ src, const int* __restrict__ dst, int e) {
    int i = (blockIdx.x * blockDim.x + threadIdx.x) * 4;
    if (i + 3 < e) {
        int4 d = *(const int4*)&dst[i];
        int4 sv = *(const int4*)&src[i];
        g_col[atomicAdd(&g_cursor[d.x], 1)] = sv.x;
        g_col[atomicAdd(&g_cursor[d.y], 1)] = sv.y;
        g_col[atomicAdd(&g_cursor[d.z], 1)] = sv.z;
        g_col[atomicAdd(&g_cursor[d.w], 1)] = sv.w;
    } else {
        for (int j = i; j < e; j++)
            g_col[atomicAdd(&g_cursor[dst[j]], 1)] = src[j];
    }
}

// ------------------------- aggregation (gather, warp per node) -------------

__global__ void gather_kernel(const float* __restrict__ hin, float* __restrict__ outf,
                              __nv_bfloat16* __restrict__ outh, __nv_bfloat16* __restrict__ outl,
                              const float* __restrict__ bias, int n, int relu) {
    int w = (blockIdx.x * blockDim.x + threadIdx.x) >> 5;
    int lane = threadIdx.x & 31;
    if (w >= n) return;
    int beg = g_rowptr[w];
    int end = g_rowptr[w + 1];
    float dv = g_dinv[w];
    float4 hv = *(const float4*)&hin[(size_t)w * H + lane * 4];
    float4 a0 = make_float4(dv * hv.x, dv * hv.y, dv * hv.z, dv * hv.w);  // self loop
    float4 a1 = make_float4(0.f, 0.f, 0.f, 0.f);
    float4 a2 = make_float4(0.f, 0.f, 0.f, 0.f);
    float4 a3 = make_float4(0.f, 0.f, 0.f, 0.f);
    for (int e0 = beg; e0 < end; e0 += 32) {
        int idx = e0 + lane;
        int c = 0;
        float dval = 0.f;
        if (idx < end) { c = g_col[idx]; dval = g_dinv[c]; }
        int m = min(32, end - e0);
        int j = 0;
        for (; j + 4 <= m; j += 4) {
            int u0 = __shfl_sync(0xffffffffu, c, j);
            int u1 = __shfl_sync(0xffffffffu, c, j + 1);
            int u2 = __shfl_sync(0xffffffffu, c, j + 2);
            int u3 = __shfl_sync(0xffffffffu, c, j + 3);
            float d0 = __shfl_sync(0xffffffffu, dval, j);
            float d1 = __shfl_sync(0xffffffffu, dval, j + 1);
            float d2 = __shfl_sync(0xffffffffu, dval, j + 2);
            float d3 = __shfl_sync(0xffffffffu, dval, j + 3);
            float4 h0v = *(const float4*)&hin[(size_t)u0 * H + lane * 4];
            float4 h1v = *(const float4*)&hin[(size_t)u1 * H + lane * 4];
            float4 h2v = *(const float4*)&hin[(size_t)u2 * H + lane * 4];
            float4 h3v = *(const float4*)&hin[(size_t)u3 * H + lane * 4];
            a0.x += d0 * h0v.x; a0.y += d0 * h0v.y; a0.z += d0 * h0v.z; a0.w += d0 * h0v.w;
            a1.x += d1 * h1v.x; a1.y += d1 * h1v.y; a1.z += d1 * h1v.z; a1.w += d1 * h1v.w;
            a2.x += d2 * h2v.x; a2.y += d2 * h2v.y; a2.z += d2 * h2v.z; a2.w += d2 * h2v.w;
            a3.x += d3 * h3v.x; a3.y += d3 * h3v.y; a3.z += d3 * h3v.z; a3.w += d3 * h3v.w;
        }
        for (; j < m; j++) {
            int u = __shfl_sync(0xffffffffu, c, j);
            float du = __shfl_sync(0xffffffffu, dval, j);
            float4 huv = *(const float4*)&hin[(size_t)u * H + lane * 4];
            a0.x += du * huv.x; a0.y += du * huv.y; a0.z += du * huv.z; a0.w += du * huv.w;
        }
    }
    float4 acc = make_float4((a0.x + a1.x) + (a2.x + a3.x),
                             (a0.y + a1.y) + (a2.y + a3.y),
                             (a0.z + a1.z) + (a2.z + a3.z),
                             (a0.w + a1.w) + (a2.w + a3.w));
    acc.x *= dv; acc.y *= dv; acc.z *= dv; acc.w *= dv;
    if (bias) {
        float4 b4 = *(const float4*)&bias[lane * 4];
        acc.x += b4.x; acc.y += b4.y; acc.z += b4.z; acc.w += b4.w;
    }
    if (relu) {
        acc.x = fmaxf(acc.x, 0.f); acc.y = fmaxf(acc.y, 0.f);
        acc.z = fmaxf(acc.z, 0.f); acc.w = fmaxf(acc.w, 0.f);
    }
    if (outf) {
        *(float4*)&outf[(size_t)w * H + lane * 4] = acc;
    } else {
        ushort4 h, l;
        split_bf16(acc.x, h.x, l.x);
        split_bf16(acc.y, h.y, l.y);
        split_bf16(acc.z, h.z, l.z);
        split_bf16(acc.w, h.w, l.w);
        *(ushort4*)&outh[(size_t)w * H + lane * 4] = h;
        *(ushort4*)&outl[(size_t)w * H + lane * 4] = l;
    }
}

// ------------------------- weight folding ----------------------------------

__global__ void wprep_kernel(const float* __restrict__ W2, const float* __restrict__ W2u,
                             const float* __restrict__ Wpca, const float* __restrict__ Wbce,
                             const float* __restrict__ b2, const float* __restrict__ b2u,
                             const float* __restrict__ bpca, const float* __restrict__ bbce) {
    int k = blockIdx.x;       // 0..127 (input dim)
    int j = threadIdx.x;      // 0..127 (output dim within segment)
    int seg = blockIdx.y;     // 0..2
    float v;
    if (seg == 0) {
        v = W2[k * H + j];
    } else if (seg == 1) {
        float s = 0.f;
        for (int m = 0; m < H; m++) s += (W2[k * H + m] + W2u[k * H + m]) * Wpca[j * H + m];
        v = s;
    } else {
        float s = 0.f;
        for (int m = 0; m < H; m++) s += W2u[k * H + m] * Wbce[j * H + m];
        v = s;
    }
    unsigned short hi, lo;
    split_bf16(v, hi, lo);
    g_Wbh[k * 384 + seg * H + j] = *(__nv_bfloat16*)&hi;
    g_Wbl[k * 384 + seg * H + j] = *(__nv_bfloat16*)&lo;
    if (k == 0) {
        float b;
        if (seg == 0) {
            b = b2[j];
        } else if (seg == 1) {
            float s = 0.f;
            for (int m = 0; m < H; m++) s += (b2[m] + b2u[m]) * Wpca[j * H + m];
            b = s + bpca[j];
        } else {
            float s = 0.f;
            for (int m = 0; m < H; m++) s += b2u[m] * Wbce[j * H + m];
            b = s + bbce[j];
        }
        g_bbig[seg * H + j] = b;
    }
}

// ------------------------- bf16-split tensor GEMM --------------------------
// D[n x 64-coltile] = A[n x 128] @ W[128 x ldw] + bias
// Block: 128 rows x 64 cols, K=128 in smem. 8 warps, warp tile 16x64.
// acc += Ah*Wh + Ah*Wl + Al*Wh  (fp32 accumulate) ~ fp32 accuracy.
// a_fp32/w_fp32: operand arrives fp32 and is hi/lo split during smem fill.
// smem 104 KB -> 2 blocks/SM from the smem footprint (load/compute overlap).

#define APAD 136  // bf16 elems per padded A row (272 B; conflict-free ldmatrix)
#define WPAD 72   // bf16 elems per padded W row (144 B)

__global__ __launch_bounds__(256)
void gemm_mma_kernel(const void* __restrict__ A0, const void* __restrict__ A1,
                     const void* __restrict__ W0, const void* __restrict__ W1p,
                     int a_fp32, int w_fp32, int ldw,
                     const float* __restrict__ bias, int n,
                     float* __restrict__ d0, float* __restrict__ d1, float* __restrict__ d2) {
    extern __shared__ unsigned short smem[];
    unsigned short* Ah_s = smem;                    // 128 x APAD
    unsigned short* Al_s = Ah_s + 128 * APAD;
    unsigned short* Wh_s = Al_s + 128 * APAD;       // 128 x WPAD
    unsigned short* Wl_s = Wh_s + 128 * WPAD;

    int tid = threadIdx.x;
    int row0 = blockIdx.x * 128;
    int colOff = blockIdx.y * 64;

    if (a_fp32) {
        const float* A = (const float*)A0;
        for (int i = tid; i < 128 * 32; i += 256) {
            int r = i >> 5;
            int c = i & 31;             // float4 chunk (4 floats)
            int gr = row0 + r;
            float4 v = make_float4(0.f, 0.f, 0.f, 0.f);
            if (gr < n) v = ((const float4*)(A + (size_t)gr * H))[c];
            ushort4 h, l;
            split_bf16(v.x, h.x, l.x);
            split_bf16(v.y, h.y, l.y);
            split_bf16(v.z, h.z, l.z);
            split_bf16(v.w, h.w, l.w);
            *(ushort4*)&Ah_s[r * APAD + c * 4] = h;
            *(ushort4*)&Al_s[r * APAD + c * 4] = l;
        }
    } else {
        const __nv_bfloat16* Ah = (const __nv_bfloat16*)A0;
        const __nv_bfloat16* Al = (const __nv_bfloat16*)A1;
        const uint4 zero4 = make_uint4(0, 0, 0, 0);
        for (int i = tid; i < 128 * 16; i += 256) {
            int r = i >> 4;
            int c = i & 15;             // 16B chunk = 8 bf16
            int gr = row0 + r;
            uint4 vh = zero4, vl = zero4;
            if (gr < n) {
                vh = ((const uint4*)(Ah + (size_t)gr * H))[c];
                vl = ((const uint4*)(Al + (size_t)gr * H))[c];
            }
            *(uint4*)&Ah_s[r * APAD + c * 8] = vh;
            *(uint4*)&Al_s[r * APAD + c * 8] = vl;
        }
    }

    if (w_fp32) {
        const float* W = (const float*)W0;
        for (int i = tid; i < 128 * 16; i += 256) {
            int k = i >> 4;
            int c = i & 15;             // float4 chunk of the 64-col slice
            float4 v = ((const float4*)(W + (size_t)k * ldw + colOff))[c];
            ushort4 h, l;
            split_bf16(v.x, h.x, l.x);
            split_bf16(v.y, h.y, l.y);
            split_bf16(v.z, h.z, l.z);
            split_bf16(v.w, h.w, l.w);
            *(ushort4*)&Wh_s[k * WPAD + c * 4] = h;
            *(ushort4*)&Wl_s[k * WPAD + c * 4] = l;
        }
    } else {
        const __nv_bfloat16* Wh = (const __nv_bfloat16*)W0;
        const __nv_bfloat16* Wl = (const __nv_bfloat16*)W1p;
        for (int i = tid; i < 128 * 8; i += 256) {
            int k = i >> 3;
            int c = i & 7;              // 16B chunk = 8 bf16
            *(uint4*)&Wh_s[k * WPAD + c * 8] = ((const uint4*)(Wh + (size_t)k * ldw + colOff))[c];
            *(uint4*)&Wl_s[k * WPAD + c * 8] = ((const uint4*)(Wl + (size_t)k * ldw + colOff))[c];
        }
    }
    __syncthreads();

    int lane = tid & 31;
    int warp = tid >> 5;
    int m0 = warp * 16;           // warp rows m0..m0+15, all 64 cols
    int lrow = lane & 15;
    int lsel = lane >> 4;

    uint32_t baseAh = (uint32_t)__cvta_generic_to_shared(&Ah_s[(m0 + lrow) * APAD + lsel * 8]);
    uint32_t baseAl = (uint32_t)__cvta_generic_to_shared(&Al_s[(m0 + lrow) * APAD + lsel * 8]);
    uint32_t baseWh = (uint32_t)__cvta_generic_to_shared(&Wh_s[lrow * WPAD + lsel * 8]);
    uint32_t baseWl = (uint32_t)__cvta_generic_to_shared(&Wl_s[lrow * WPAD + lsel * 8]);

    float acc[8][4];
#pragma unroll
    for (int nt = 0; nt < 8; nt++)
#pragma unroll
        for (int q = 0; q < 4; q++) acc[nt][q] = 0.f;

    for (int k0 = 0; k0 < 128; k0 += 16) {
        uint32_t ah[4], al[4], wh[8][2], wl[8][2];
        ldsm4(ah[0], ah[1], ah[2], ah[3], baseAh + (uint32_t)k0 * 2);
        ldsm4(al[0], al[1], al[2], al[3], baseAl + (uint32_t)k0 * 2);
#pragma unroll
        for (int nt2 = 0; nt2 < 4; nt2++) {
            uint32_t off = (uint32_t)(k0 * WPAD + nt2 * 16) * 2;
            ldsm4t(wh[2 * nt2][0], wh[2 * nt2][1], wh[2 * nt2 + 1][0], wh[2 * nt2 + 1][1],
                   baseWh + off);
            ldsm4t(wl[2 * nt2][0], wl[2 * nt2][1], wl[2 * nt2 + 1][0], wl[2 * nt2 + 1][1],
                   baseWl + off);
        }
#pragma unroll
        for (int nt = 0; nt < 8; nt++) {
            mma_bf16(acc[nt], ah, wh[nt]);
            mma_bf16(acc[nt], ah, wl[nt]);
            mma_bf16(acc[nt], al, wh[nt]);
        }
    }

    // epilogue: 64-col tile lies in exactly one output segment
    int seg = colOff >> 7;
    float* dst = (seg == 0) ? d0 : ((seg == 1) ? d1 : d2);
    int jbase = colOff & 127;
    int g = lane >> 2;
    int tg = lane & 3;
#pragma unroll
    for (int nt = 0; nt < 8; nt++) {
        int colL = nt * 8 + 2 * tg;
        float bx = 0.f, by = 0.f;
        if (bias) { bx = bias[colOff + colL]; by = bias[colOff + colL + 1]; }
        int gr0 = row0 + m0 + g;
        if (gr0 < n) {
            float2 o = make_float2(acc[nt][0] + bx, acc[nt][1] + by);
            *(float2*)&dst[(size_t)gr0 * H + jbase + colL] = o;
        }
        int gr1 = gr0 + 8;
        if (gr1 < n) {
            float2 o = make_float2(acc[nt][2] + bx, acc[nt][3] + by);
            *(float2*)&dst[(size_t)gr1 * H + jbase + colL] = o;
        }
    }
}

// ------------------------- out1 head ---------------------------------------

__global__ void out1_kernel(const float* __restrict__ fl, const float* __restrict__ Wh1,
                            const float* __restrict__ bh1, float* __restrict__ out1, int n) {
    int w = (blockIdx.x * blockDim.x + threadIdx.x) >> 5;
    int lane = threadIdx.x & 31;
    if (w >= n) return;
    float4 f = *(const float4*)&fl[(size_t)w * H + lane * 4];
    float ss = f.x * f.x + f.y * f.y + f.z * f.z + f.w * f.w;
#pragma unroll
    for (int off = 16; off > 0; off >>= 1) ss += __shfl_xor_sync(0xffffffffu, ss, off);
    float nrm = fmaxf(sqrtf(ss), 1e-12f);
    float inv = 10.f / nrm;
#pragma unroll
    for (int j = 0; j < 4; j++) {
        float4 wv = *(const float4*)&Wh1[j * H + lane * 4];
        float p = f.x * wv.x + f.y * wv.y + f.z * wv.z + f.w * wv.w;
#pragma unroll
        for (int off = 16; off > 0; off >>= 1) p += __shfl_xor_sync(0xffffffffu, p, off);
        if (lane == 0) out1[(size_t)w * 4 + j] = p * inv + bh1[j] * 10.f;
    }
}

// ------------------------- launch ------------------------------------------

extern "C" void kernel_launch(void* const* d_in, const int* in_sizes, int n_in,
                              void* d_out, int out_size) {
    const float* x    = (const float*)d_in[0];
    const int*   ei   = (const int*)d_in[1];
    const float* W1   = (const float*)d_in[2];
    const float* b1   = (const float*)d_in[3];
    const float* W2   = (const float*)d_in[4];
    const float* b2   = (const float*)d_in[5];
    const float* W2u  = (const float*)d_in[6];
    const float* b2u  = (const float*)d_in[7];
    const float* Wh1  = (const float*)d_in[8];
    const float* bh1  = (const float*)d_in[9];
    const float* Wpca = (const float*)d_in[10];
    const float* bpca = (const float*)d_in[11];
    const float* Wbce = (const float*)d_in[12];
    const float* bbce = (const float*)d_in[13];

    int n = in_sizes[0] / H;
    int e = in_sizes[1] / 2;
    const int* src = ei;
    const int* dst = ei + e;

    float* out  = (float*)d_out;
    float* out1 = out;
    float* opca = out + (size_t)n * 4;
    float* obce = opca + (size_t)n * H;
    float* flab = obce + (size_t)n * H;

    void *p_h0, *p_h, *p_aggh, *p_aggl, *p_Wbh, *p_Wbl, *p_bbig;
    cudaGetSymbolAddress(&p_h0, g_h0);
    cudaGetSymbolAddress(&p_h, g_h);
    cudaGetSymbolAddress(&p_aggh, g_aggh);
    cudaGetSymbolAddress(&p_aggl, g_aggl);
    cudaGetSymbolAddress(&p_Wbh, g_Wbh);
    cudaGetSymbolAddress(&p_Wbl, g_Wbl);
    cudaGetSymbolAddress(&p_bbig, g_bbig);

    const int smem_gemm = (2 * 128 * APAD + 2 * 128 * WPAD) * 2;  // 106496 B
    cudaFuncSetAttribute(gemm_mma_kernel, cudaFuncAttributeMaxDynamicSharedMemorySize, smem_gemm);

    int nb_n = (n + 255) / 256;
    int nb_e4 = (e + 1023) / 1024;     // 4 edges per thread
    int nb_w = (n + 7) / 8;            // warp-per-node, 256 threads = 8 warps
    int nb_g = (n + 127) / 128;        // gemm row tiles
    int nb_s = (n + 1023) / 1024;      // scan blocks

    // graph prep
    zero_deg_kernel<<<nb_n, 256>>>(n);
    hist_kernel<<<nb_e4, 256>>>(dst, e);
    blockscan_kernel<<<nb_s, 256>>>(n);    // also emits dinv
    bsum_scan_kernel<<<1, 64>>>(nb_s);
    addoff_kernel<<<nb_n, 256>>>(n, e);
    scatter_kernel<<<nb_e4, 256>>>(src, dst, e);

    // layer 1: h0 = x @ W1 (fp32 in, split in-kernel), h = relu(Agg(h0) + b1)
    gemm_mma_kernel<<<dim3(nb_g, 2), 256, smem_gemm>>>(
        x, nullptr, W1, nullptr, 1, 1, H, nullptr, n,
        (float*)p_h0, (float*)p_h0, (float*)p_h0);
    gather_kernel<<<nb_w, 256>>>((const float*)p_h0, (float*)p_h, nullptr, nullptr, b1, n, 1);

    // fold layer-2 + head weights (bf16 split)
    wprep_kernel<<<dim3(H, 3), H>>>(W2, W2u, Wpca, Wbce, b2, b2u, bpca, bbce);

    // layer 2: agg = Agg(h) (split bf16 out) ; fused GEMM -> flab/opca/obce
    gather_kernel<<<nb_w, 256>>>((const float*)p_h, nullptr,
                                 (__nv_bfloat16*)p_aggh, (__nv_bfloat16*)p_aggl, nullptr, n, 0);
    gemm_mma_kernel<<<dim3(nb_g, 6), 256, smem_gemm>>>(
        (const void*)p_aggh, (const void*)p_aggl, (const void*)p_Wbh, (const void*)p_Wbl,
        0, 0, 384, (const float*)p_bbig, n, flab, opca, obce);

    // out1 head from feat_label
    out1_kernel<<<nb_w, 256>>>(flab, Wh1, bh1, out1, n);
}